// round 8
// baseline (speedup 1.0000x reference)
#include <cuda_runtime.h>
#include <cstdint>

// Problem constants (fixed by the reference)
#define NMAX 100000
#define EMAX 1250000
#define HDIM 64
#define NCLS 10

// Scratch: __device__ globals (allocation APIs are forbidden).
__device__ __align__(16) float g_t2[NMAX * HDIM];   // matmul output (pre-scaled messages)
__device__ __align__(16) float g_h [NMAX * HDIM];   // layer output
__device__ float g_dinv[NMAX];
__device__ int   g_cnt[NMAX];
__device__ int   g_rowptr[NMAX + 1];
__device__ int   g_eidx[EMAX];

// ---------------------------------------------------------------------------
__global__ void k_zerocnt(int n) {
    int i = blockIdx.x * blockDim.x + threadIdx.x;
    if (i < n) g_cnt[i] = 0;
}

// in-degree histogram over dst (guarded: bad index -> skipped, shows as rel_err)
__global__ void k_hist(const int* __restrict__ ei, int e, int n) {
    int idx = blockIdx.x * blockDim.x + threadIdx.x;
    if (idx < e) {
        int d = ei[e + idx];
        if (d >= 0 && d < n) atomicAdd(&g_cnt[d], 1);
    }
}

// dinv[i] = rsqrt(deg[i]) with deg = in-degree + 1 (self loop)
__global__ void k_dinvk(int n) {
    int i = blockIdx.x * blockDim.x + threadIdx.x;
    if (i < n) g_dinv[i] = rsqrtf((float)(g_cnt[i] + 1));
}

// Exclusive scan of g_cnt -> g_rowptr, single block of 1024 threads.
// Also zeroes g_cnt (reused as fill cursor).
__global__ void k_scan(int n) {
    __shared__ int ssum[1024];
    const int t = threadIdx.x;
    const int chunk = (n + 1023) >> 10;
    const int beg = min(n, t * chunk);
    const int end = min(n, beg + chunk);

    int s = 0;
    for (int i = beg; i < end; i++) s += g_cnt[i];
    ssum[t] = s;
    __syncthreads();

    // Hillis-Steele inclusive scan
    for (int off = 1; off < 1024; off <<= 1) {
        int v = 0;
        if (t >= off) v = ssum[t - off];
        __syncthreads();
        if (t >= off) ssum[t] += v;
        __syncthreads();
    }

    int run = (t == 0) ? 0 : ssum[t - 1];
    for (int i = beg; i < end; i++) {
        int c = g_cnt[i];
        g_rowptr[i] = run;
        run += c;
        g_cnt[i] = 0;
    }
    if (t == 1023) g_rowptr[n] = ssum[1023];
}

// Scatter edges into CSR slots (by dst). Order within a row is arbitrary.
__global__ void k_fill(const int* __restrict__ ei, int e, int n) {
    int idx = blockIdx.x * blockDim.x + threadIdx.x;
    if (idx < e) {
        int s = ei[idx];
        int d = ei[e + idx];
        if (s >= 0 && s < n && d >= 0 && d < n) {
            int pos = g_rowptr[d] + atomicAdd(&g_cnt[d], 1);
            if (pos < EMAX) g_eidx[pos] = s;
        }
    }
}

// ---------------------------------------------------------------------------
// t2 = dinv ⊙ ((relu?)hin @ W)
// 64-row tile per block, 256 threads: thread = (row = tid/4, 16-col block = tid%4)
__global__ void k_matmul(const float* __restrict__ xin, int use_x,
                         const float* __restrict__ W, int n, int relu) {
    __shared__ float Hsh[64 * 68];   // stride 68: 16B-aligned rows, conflict-free
    __shared__ float Wsh[64 * 64];

    const float* hin = use_x ? xin : g_h;

    const int tid = threadIdx.x;
    const int r0  = blockIdx.x * 64;

    // Load W (64x64) coalesced
    const float4* W4 = (const float4*)W;
    float4* Wsh4 = (float4*)Wsh;
#pragma unroll
    for (int i = 0; i < 4; i++) Wsh4[tid + 256 * i] = W4[tid + 256 * i];

    // Load H tile (64 rows x 64 cols), optional relu
#pragma unroll
    for (int i = 0; i < 4; i++) {
        int idx = tid + 256 * i;         // 0..1023 float4 slots
        int row = idx >> 4;
        int c4  = idx & 15;
        int gr  = r0 + row;
        float4 v = make_float4(0.f, 0.f, 0.f, 0.f);
        if (gr < n) v = *(const float4*)(hin + (size_t)gr * 64 + c4 * 4);
        if (relu) {
            v.x = fmaxf(v.x, 0.f); v.y = fmaxf(v.y, 0.f);
            v.z = fmaxf(v.z, 0.f); v.w = fmaxf(v.w, 0.f);
        }
        float* hp = &Hsh[row * 68 + c4 * 4];
        hp[0] = v.x; hp[1] = v.y; hp[2] = v.z; hp[3] = v.w;
    }
    __syncthreads();

    const int row = tid >> 2;          // 0..63
    const int cb  = (tid & 3) * 16;    // col base
    float acc[16];
#pragma unroll
    for (int j = 0; j < 16; j++) acc[j] = 0.f;

#pragma unroll 16
    for (int k = 0; k < 64; k++) {
        float hk = Hsh[row * 68 + k];
#pragma unroll
        for (int j = 0; j < 16; j++)
            acc[j] = fmaf(hk, Wsh[k * 64 + cb + j], acc[j]);
    }

    const int gr = r0 + row;
    if (gr < n) {
        float di = g_dinv[gr];
        size_t base = (size_t)gr * 64 + cb;
#pragma unroll
        for (int j = 0; j < 16; j += 4) {
            float4 t;
            t.x = di * acc[j + 0]; t.y = di * acc[j + 1];
            t.z = di * acc[j + 2]; t.w = di * acc[j + 3];
            *(float4*)(g_t2 + base + j) = t;
        }
    }
}

// ---------------------------------------------------------------------------
// Gather aggregation: h[i] = dinv[i]*(t2[i] + sum_{e: dst=i} t2[src_e]) + b
// 16 threads per node, float4 per thread.
__global__ void k_gather(const float* __restrict__ b, int n) {
    int gid = blockIdx.x * blockDim.x + threadIdx.x;
    int node = gid >> 4;
    if (node >= n) return;
    int q = (gid & 15) << 2;

    const float* t2 = g_t2;
    float4 acc = *(const float4*)(t2 + ((size_t)node << 6) + q);

    int k   = g_rowptr[node];
    int end = g_rowptr[node + 1];

    // 2-way unrolled for MLP
    for (; k + 2 <= end; k += 2) {
        int s0 = __ldg(&g_eidx[k]);
        int s1 = __ldg(&g_eidx[k + 1]);
        float4 v0 = *(const float4*)(t2 + ((size_t)s0 << 6) + q);
        float4 v1 = *(const float4*)(t2 + ((size_t)s1 << 6) + q);
        acc.x += v0.x + v1.x;
        acc.y += v0.y + v1.y;
        acc.z += v0.z + v1.z;
        acc.w += v0.w + v1.w;
    }
    if (k < end) {
        int s0 = __ldg(&g_eidx[k]);
        float4 v0 = *(const float4*)(t2 + ((size_t)s0 << 6) + q);
        acc.x += v0.x; acc.y += v0.y; acc.z += v0.z; acc.w += v0.w;
    }

    float di = g_dinv[node];
    float4 bb = *(const float4*)(b + q);
    float4 o;
    o.x = fmaf(di, acc.x, bb.x);
    o.y = fmaf(di, acc.y, bb.y);
    o.z = fmaf(di, acc.z, bb.z);
    o.w = fmaf(di, acc.w, bb.w);
    *(float4*)(g_h + ((size_t)node << 6) + q) = o;
}

// ---------------------------------------------------------------------------
// Fused mean-pool (batch sorted -> binary search segments) + linear head.
// One block per graph: 256 threads = 64 cols x 4 node-strides.
__global__ void k_pool(const int* __restrict__ batch,
                       const float* __restrict__ Wl, const float* __restrict__ bl,
                       float* __restrict__ out, int n) {
    const float* h = g_h;
    const int g = blockIdx.x;
    const int t = threadIdx.x;
    const int c = t & 63;
    const int j = t >> 6;

    auto lb = [&](int key) {
        int lo = 0, hi = n;
        while (lo < hi) {
            int mid = (lo + hi) >> 1;
            if (batch[mid] < key) lo = mid + 1; else hi = mid;
        }
        return lo;
    };
    int lo = lb(g);
    int hi = lb(g + 1);
    int cnt = hi - lo;

    float s = 0.f;
    for (int i = lo + j; i < hi; i += 4)
        s += h[(size_t)i * 64 + c];

    __shared__ float red[256];
    red[t] = s;
    __syncthreads();

    __shared__ float pooled[64];
    if (t < 64) {
        float tot = red[t] + red[t + 64] + red[t + 128] + red[t + 192];
        pooled[t] = tot / (float)max(cnt, 1);
    }
    __syncthreads();

    if (t < NCLS) {
        float acc = bl[t];
#pragma unroll
        for (int k = 0; k < 64; k++)
            acc = fmaf(pooled[k], Wl[k * NCLS + t], acc);
        out[g * NCLS + t] = acc;
    }
}

// ---------------------------------------------------------------------------
extern "C" void kernel_launch(void* const* d_in, const int* in_sizes, int n_in,
                              void* d_out, int out_size) {
    // Resolve inputs BY ELEMENT COUNT (robust to metadata ordering).
    // Counts: x=6.4M, edge_index=2.5M (int32!), batch=100K (int32!),
    //         W1/W2/W3=4096 (encounter order), b1/b2/b3=64 (encounter order),
    //         Wl=640, bl=10.
    const float* x     = nullptr;
    const int*   ei    = nullptr;
    const int*   batch = nullptr;
    const float* W[3] = {nullptr, nullptr, nullptr};
    const float* B[3] = {nullptr, nullptr, nullptr};
    const float* Wl = nullptr;
    const float* bl = nullptr;
    int nW = 0, nB = 0;
    long long eiCount = 0, batchCount = 0;

    for (int i = 0; i < n_in; i++) {
        long long sz = in_sizes[i];
        if (sz == 10)            bl = (const float*)d_in[i];
        else if (sz == 640)      Wl = (const float*)d_in[i];
        else if (sz == HDIM)     { if (nB < 3) B[nB++] = (const float*)d_in[i]; }
        else if (sz == HDIM*HDIM){ if (nW < 3) W[nW++] = (const float*)d_in[i]; }
        else {
            // large arrays: distinguish by element count
            if (sz >= 6000000)       x = (const float*)d_in[i];
            else if (sz >= 2000000)  { ei = (const int*)d_in[i]; eiCount = sz; }
            else                     { batch = (const int*)d_in[i]; batchCount = sz; }
        }
    }

    float* out = (float*)d_out;
    const int n = (int)batchCount;            // N nodes
    const int e = (int)(eiCount / 2);         // E edges
    const int g = out_size / NCLS;            // G graphs

    const int tb = 256;

    // CSR build + dinv
    k_zerocnt<<<(n + tb - 1) / tb, tb>>>(n);
    k_hist   <<<(e + tb - 1) / tb, tb>>>(ei, e, n);
    k_dinvk  <<<(n + tb - 1) / tb, tb>>>(n);
    k_scan   <<<1, 1024>>>(n);
    k_fill   <<<(e + tb - 1) / tb, tb>>>(ei, e, n);

    const int mmGrid = (n + 63) / 64;
    const int gaGrid = (n * 16 + tb - 1) / tb;

    // Layer 1: x -> t2 -> h
    k_matmul<<<mmGrid, tb>>>(x, 1, W[0], n, 0);
    k_gather<<<gaGrid, tb>>>(B[0], n);
    // Layer 2: h(relu) -> t2 -> h
    k_matmul<<<mmGrid, tb>>>(nullptr, 0, W[1], n, 1);
    k_gather<<<gaGrid, tb>>>(B[1], n);
    // Layer 3: h(relu) -> t2 -> h
    k_matmul<<<mmGrid, tb>>>(nullptr, 0, W[2], n, 1);
    k_gather<<<gaGrid, tb>>>(B[2], n);

    // Pool + head
    k_pool<<<g, tb>>>(batch, Wl, bl, out, n);
}

// round 9
// speedup vs baseline: 1.2683x; 1.2683x over previous
#include <cuda_runtime.h>
#include <cstdint>

// Problem constants (fixed by the reference)
#define NMAX 100000
#define EMAX 1250000
#define HDIM 64
#define NCLS 10
#define SCAN_CHUNK 1024
#define MAXBLK 128   // ceil(NMAX/SCAN_CHUNK) = 98 <= 128

// Scratch: __device__ globals (allocation APIs are forbidden).
__device__ __align__(16) float g_t2[NMAX * HDIM];   // matmul output (pre-scaled messages)
__device__ __align__(16) float g_h [NMAX * HDIM];   // layer output
__device__ float g_dinv[NMAX];
__device__ int   g_cnt[NMAX];
__device__ int   g_rowptr[NMAX + 1];
__device__ int   g_eidx[EMAX];
__device__ int   g_bsum[MAXBLK];
__device__ int   g_boff[MAXBLK];

// ---------------------------------------------------------------------------
__global__ void k_zerocnt(int n) {
    int i = blockIdx.x * blockDim.x + threadIdx.x;
    if (i < n) g_cnt[i] = 0;
}

// in-degree histogram over dst (guarded: bad index -> skipped, shows as rel_err)
__global__ void k_hist(const int* __restrict__ ei, int e, int n) {
    int idx = blockIdx.x * blockDim.x + threadIdx.x;
    if (idx < e) {
        int d = ei[e + idx];
        if (d >= 0 && d < n) atomicAdd(&g_cnt[d], 1);
    }
}

// dinv[i] = rsqrt(deg[i]) with deg = in-degree + 1 (self loop)
__global__ void k_dinvk(int n) {
    int i = blockIdx.x * blockDim.x + threadIdx.x;
    if (i < n) g_dinv[i] = rsqrtf((float)(g_cnt[i] + 1));
}

// ---------------------------------------------------------------------------
// Parallel 3-phase exclusive scan of g_cnt -> g_rowptr.
// Phase 1: per-block sums (1024 counts per block, 256 threads).
__global__ void k_blocksum(int n) {
    const int t = threadIdx.x;
    const int base = blockIdx.x * SCAN_CHUNK + t * 4;
    int s = 0;
#pragma unroll
    for (int j = 0; j < 4; j++) {
        int i = base + j;
        if (i < n) s += g_cnt[i];
    }
#pragma unroll
    for (int off = 16; off > 0; off >>= 1)
        s += __shfl_down_sync(0xffffffffu, s, off);
    __shared__ int wsum[8];
    if ((t & 31) == 0) wsum[t >> 5] = s;
    __syncthreads();
    if (t == 0) {
        int tot = 0;
#pragma unroll
        for (int w = 0; w < 8; w++) tot += wsum[w];
        g_bsum[blockIdx.x] = tot;
    }
}

// Phase 2: one small block scans the block sums (nb <= 128).
__global__ void k_scanb(int nb, int n) {
    const int t = threadIdx.x;       // 128 threads
    int v = (t < nb) ? g_bsum[t] : 0;
    int own = v;
    int lane = t & 31, w = t >> 5;
#pragma unroll
    for (int off = 1; off < 32; off <<= 1) {
        int u = __shfl_up_sync(0xffffffffu, v, off);
        if (lane >= off) v += u;
    }
    __shared__ int wtot[4], woff[4];
    if (lane == 31) wtot[w] = v;
    __syncthreads();
    if (t == 0) {
        int run = 0;
#pragma unroll
        for (int i = 0; i < 4; i++) { woff[i] = run; run += wtot[i]; }
        g_rowptr[n] = run;           // total edge count
    }
    __syncthreads();
    int incl = v + woff[w];
    if (t < nb) g_boff[t] = incl - own;   // exclusive
}

// Phase 3: per-block local exclusive scan + block offset -> rowptr; zero cnt.
__global__ void k_rowptr(int n) {
    const int t = threadIdx.x;       // 256 threads
    const int base = blockIdx.x * SCAN_CHUNK + t * 4;
    int c[4];
    int s = 0;
#pragma unroll
    for (int j = 0; j < 4; j++) {
        int i = base + j;
        c[j] = (i < n) ? g_cnt[i] : 0;
        s += c[j];
    }
    int v = s, own = s;
    int lane = t & 31, w = t >> 5;
#pragma unroll
    for (int off = 1; off < 32; off <<= 1) {
        int u = __shfl_up_sync(0xffffffffu, v, off);
        if (lane >= off) v += u;
    }
    __shared__ int wtot[8], woff[8];
    if (lane == 31) wtot[w] = v;
    __syncthreads();
    if (t == 0) {
        int run = 0;
#pragma unroll
        for (int i = 0; i < 8; i++) { woff[i] = run; run += wtot[i]; }
    }
    __syncthreads();
    int excl = (v - own) + woff[w] + g_boff[blockIdx.x];
#pragma unroll
    for (int j = 0; j < 4; j++) {
        int i = base + j;
        if (i < n) {
            g_rowptr[i] = excl;
            excl += c[j];
            g_cnt[i] = 0;            // reset fill cursor
        }
    }
}

// Scatter edges into CSR slots (by dst). Order within a row is arbitrary.
__global__ void k_fill(const int* __restrict__ ei, int e, int n) {
    int idx = blockIdx.x * blockDim.x + threadIdx.x;
    if (idx < e) {
        int s = ei[idx];
        int d = ei[e + idx];
        if (s >= 0 && s < n && d >= 0 && d < n) {
            int pos = g_rowptr[d] + atomicAdd(&g_cnt[d], 1);
            if (pos < EMAX) g_eidx[pos] = s;
        }
    }
}

// ---------------------------------------------------------------------------
// t2 = dinv ⊙ ((relu?)hin @ W)
// 64-row tile per block, 256 threads: thread = (row = tid/4, 16-col block = tid%4)
__global__ void k_matmul(const float* __restrict__ xin, int use_x,
                         const float* __restrict__ W, int n, int relu) {
    __shared__ float Hsh[64 * 68];   // stride 68: 16B-aligned rows, conflict-free
    __shared__ float Wsh[64 * 64];

    const float* hin = use_x ? xin : g_h;

    const int tid = threadIdx.x;
    const int r0  = blockIdx.x * 64;

    // Load W (64x64) coalesced
    const float4* W4 = (const float4*)W;
    float4* Wsh4 = (float4*)Wsh;
#pragma unroll
    for (int i = 0; i < 4; i++) Wsh4[tid + 256 * i] = W4[tid + 256 * i];

    // Load H tile (64 rows x 64 cols), optional relu
#pragma unroll
    for (int i = 0; i < 4; i++) {
        int idx = tid + 256 * i;         // 0..1023 float4 slots
        int row = idx >> 4;
        int c4  = idx & 15;
        int gr  = r0 + row;
        float4 v = make_float4(0.f, 0.f, 0.f, 0.f);
        if (gr < n) v = *(const float4*)(hin + (size_t)gr * 64 + c4 * 4);
        if (relu) {
            v.x = fmaxf(v.x, 0.f); v.y = fmaxf(v.y, 0.f);
            v.z = fmaxf(v.z, 0.f); v.w = fmaxf(v.w, 0.f);
        }
        float* hp = &Hsh[row * 68 + c4 * 4];
        hp[0] = v.x; hp[1] = v.y; hp[2] = v.z; hp[3] = v.w;
    }
    __syncthreads();

    const int row = tid >> 2;          // 0..63
    const int cb  = (tid & 3) * 16;    // col base
    float acc[16];
#pragma unroll
    for (int j = 0; j < 16; j++) acc[j] = 0.f;

#pragma unroll 16
    for (int k = 0; k < 64; k++) {
        float hk = Hsh[row * 68 + k];
#pragma unroll
        for (int j = 0; j < 16; j++)
            acc[j] = fmaf(hk, Wsh[k * 64 + cb + j], acc[j]);
    }

    const int gr = r0 + row;
    if (gr < n) {
        float di = g_dinv[gr];
        size_t base = (size_t)gr * 64 + cb;
#pragma unroll
        for (int j = 0; j < 16; j += 4) {
            float4 t;
            t.x = di * acc[j + 0]; t.y = di * acc[j + 1];
            t.z = di * acc[j + 2]; t.w = di * acc[j + 3];
            *(float4*)(g_t2 + base + j) = t;
        }
    }
}

// ---------------------------------------------------------------------------
// Gather aggregation: h[i] = dinv[i]*(t2[i] + sum_{e: dst=i} t2[src_e]) + b
// 16 threads per node, float4 per thread, 4-way unrolled for MLP.
__global__ void k_gather(const float* __restrict__ b, int n) {
    int gid = blockIdx.x * blockDim.x + threadIdx.x;
    int node = gid >> 4;
    if (node >= n) return;
    int q = (gid & 15) << 2;

    const float* t2 = g_t2;
    float4 acc = *(const float4*)(t2 + ((size_t)node << 6) + q);
    float4 acc2 = make_float4(0.f, 0.f, 0.f, 0.f);

    int k   = g_rowptr[node];
    int end = g_rowptr[node + 1];

    for (; k + 4 <= end; k += 4) {
        int s0 = __ldg(&g_eidx[k]);
        int s1 = __ldg(&g_eidx[k + 1]);
        int s2 = __ldg(&g_eidx[k + 2]);
        int s3 = __ldg(&g_eidx[k + 3]);
        float4 v0 = *(const float4*)(t2 + ((size_t)s0 << 6) + q);
        float4 v1 = *(const float4*)(t2 + ((size_t)s1 << 6) + q);
        float4 v2 = *(const float4*)(t2 + ((size_t)s2 << 6) + q);
        float4 v3 = *(const float4*)(t2 + ((size_t)s3 << 6) + q);
        acc.x  += v0.x + v1.x;  acc.y  += v0.y + v1.y;
        acc.z  += v0.z + v1.z;  acc.w  += v0.w + v1.w;
        acc2.x += v2.x + v3.x;  acc2.y += v2.y + v3.y;
        acc2.z += v2.z + v3.z;  acc2.w += v2.w + v3.w;
    }
    for (; k < end; k++) {
        int s0 = __ldg(&g_eidx[k]);
        float4 v0 = *(const float4*)(t2 + ((size_t)s0 << 6) + q);
        acc.x += v0.x; acc.y += v0.y; acc.z += v0.z; acc.w += v0.w;
    }
    acc.x += acc2.x; acc.y += acc2.y; acc.z += acc2.z; acc.w += acc2.w;

    float di = g_dinv[node];
    float4 bb = *(const float4*)(b + q);
    float4 o;
    o.x = fmaf(di, acc.x, bb.x);
    o.y = fmaf(di, acc.y, bb.y);
    o.z = fmaf(di, acc.z, bb.z);
    o.w = fmaf(di, acc.w, bb.w);
    *(float4*)(g_h + ((size_t)node << 6) + q) = o;
}

// ---------------------------------------------------------------------------
// Fused mean-pool (batch sorted -> binary search segments) + linear head.
// One block per graph: 256 threads = 64 cols x 4 node-strides.
__global__ void k_pool(const int* __restrict__ batch,
                       const float* __restrict__ Wl, const float* __restrict__ bl,
                       float* __restrict__ out, int n) {
    const float* h = g_h;
    const int g = blockIdx.x;
    const int t = threadIdx.x;
    const int c = t & 63;
    const int j = t >> 6;

    auto lb = [&](int key) {
        int lo = 0, hi = n;
        while (lo < hi) {
            int mid = (lo + hi) >> 1;
            if (batch[mid] < key) lo = mid + 1; else hi = mid;
        }
        return lo;
    };
    int lo = lb(g);
    int hi = lb(g + 1);
    int cnt = hi - lo;

    float s = 0.f;
    for (int i = lo + j; i < hi; i += 4)
        s += h[(size_t)i * 64 + c];

    __shared__ float red[256];
    red[t] = s;
    __syncthreads();

    __shared__ float pooled[64];
    if (t < 64) {
        float tot = red[t] + red[t + 64] + red[t + 128] + red[t + 192];
        pooled[t] = tot / (float)max(cnt, 1);
    }
    __syncthreads();

    if (t < NCLS) {
        float acc = bl[t];
#pragma unroll
        for (int k = 0; k < 64; k++)
            acc = fmaf(pooled[k], Wl[k * NCLS + t], acc);
        out[g * NCLS + t] = acc;
    }
}

// ---------------------------------------------------------------------------
extern "C" void kernel_launch(void* const* d_in, const int* in_sizes, int n_in,
                              void* d_out, int out_size) {
    // Resolve inputs BY ELEMENT COUNT (robust to metadata ordering).
    const float* x     = nullptr;
    const int*   ei    = nullptr;
    const int*   batch = nullptr;
    const float* W[3] = {nullptr, nullptr, nullptr};
    const float* B[3] = {nullptr, nullptr, nullptr};
    const float* Wl = nullptr;
    const float* bl = nullptr;
    int nW = 0, nB = 0;
    long long eiCount = 0, batchCount = 0;

    for (int i = 0; i < n_in; i++) {
        long long sz = in_sizes[i];
        if (sz == 10)            bl = (const float*)d_in[i];
        else if (sz == 640)      Wl = (const float*)d_in[i];
        else if (sz == HDIM)     { if (nB < 3) B[nB++] = (const float*)d_in[i]; }
        else if (sz == HDIM*HDIM){ if (nW < 3) W[nW++] = (const float*)d_in[i]; }
        else {
            if (sz >= 6000000)       x = (const float*)d_in[i];
            else if (sz >= 2000000)  { ei = (const int*)d_in[i]; eiCount = sz; }
            else                     { batch = (const int*)d_in[i]; batchCount = sz; }
        }
    }

    float* out = (float*)d_out;
    const int n = (int)batchCount;            // N nodes
    const int e = (int)(eiCount / 2);         // E edges
    const int g = out_size / NCLS;            // G graphs

    const int tb = 256;
    const int nb = (n + SCAN_CHUNK - 1) / SCAN_CHUNK;   // scan blocks (98)

    // CSR build + dinv
    k_zerocnt <<<(n + tb - 1) / tb, tb>>>(n);
    k_hist    <<<(e + tb - 1) / tb, tb>>>(ei, e, n);
    k_dinvk   <<<(n + tb - 1) / tb, tb>>>(n);
    k_blocksum<<<nb, tb>>>(n);
    k_scanb   <<<1, 128>>>(nb, n);
    k_rowptr  <<<nb, tb>>>(n);
    k_fill    <<<(e + tb - 1) / tb, tb>>>(ei, e, n);

    const int mmGrid = (n + 63) / 64;
    const int gaGrid = (n * 16 + tb - 1) / tb;

    // Layer 1: x -> t2 -> h
    k_matmul<<<mmGrid, tb>>>(x, 1, W[0], n, 0);
    k_gather<<<gaGrid, tb>>>(B[0], n);
    // Layer 2: h(relu) -> t2 -> h
    k_matmul<<<mmGrid, tb>>>(nullptr, 0, W[1], n, 1);
    k_gather<<<gaGrid, tb>>>(B[1], n);
    // Layer 3: h(relu) -> t2 -> h
    k_matmul<<<mmGrid, tb>>>(nullptr, 0, W[2], n, 1);
    k_gather<<<gaGrid, tb>>>(B[2], n);

    // Pool + head
    k_pool<<<g, tb>>>(batch, Wl, bl, out, n);
}

// round 10
// speedup vs baseline: 1.3579x; 1.0706x over previous
#include <cuda_runtime.h>
#include <cuda_fp16.h>
#include <cstdint>

// Problem constants (fixed by the reference)
#define NMAX 100000
#define EMAX 1250000
#define HDIM 64
#define NCLS 10
#define SCAN_CHUNK 1024
#define MAXBLK 128   // ceil(NMAX/SCAN_CHUNK) = 98 <= 128

// Scratch: __device__ globals (allocation APIs are forbidden).
__device__ __align__(16)  float  g_t2[NMAX * HDIM];   // fp32 messages (self term)
__device__ __align__(128) __half g_t2h[NMAX * HDIM];  // fp16 messages (neighbor reads)
__device__ __align__(16)  float  g_h [NMAX * HDIM];   // layer output
__device__ float g_dinv[NMAX];
__device__ int   g_cnt[NMAX];
__device__ int   g_rowptr[NMAX + 1];
__device__ int   g_eidx[EMAX];
__device__ int   g_bsum[MAXBLK];
__device__ int   g_boff[MAXBLK];

// ---------------------------------------------------------------------------
__global__ void k_zerocnt(int n) {
    int i = blockIdx.x * blockDim.x + threadIdx.x;
    if (i < n) g_cnt[i] = 0;
}

// in-degree histogram over dst (guarded: bad index -> skipped, shows as rel_err)
__global__ void k_hist(const int* __restrict__ ei, int e, int n) {
    int idx = blockIdx.x * blockDim.x + threadIdx.x;
    if (idx < e) {
        int d = ei[e + idx];
        if (d >= 0 && d < n) atomicAdd(&g_cnt[d], 1);
    }
}

// dinv[i] = rsqrt(deg[i]) with deg = in-degree + 1 (self loop)
__global__ void k_dinvk(int n) {
    int i = blockIdx.x * blockDim.x + threadIdx.x;
    if (i < n) g_dinv[i] = rsqrtf((float)(g_cnt[i] + 1));
}

// ---------------------------------------------------------------------------
// Parallel 3-phase exclusive scan of g_cnt -> g_rowptr.
__global__ void k_blocksum(int n) {
    const int t = threadIdx.x;
    const int base = blockIdx.x * SCAN_CHUNK + t * 4;
    int s = 0;
#pragma unroll
    for (int j = 0; j < 4; j++) {
        int i = base + j;
        if (i < n) s += g_cnt[i];
    }
#pragma unroll
    for (int off = 16; off > 0; off >>= 1)
        s += __shfl_down_sync(0xffffffffu, s, off);
    __shared__ int wsum[8];
    if ((t & 31) == 0) wsum[t >> 5] = s;
    __syncthreads();
    if (t == 0) {
        int tot = 0;
#pragma unroll
        for (int w = 0; w < 8; w++) tot += wsum[w];
        g_bsum[blockIdx.x] = tot;
    }
}

__global__ void k_scanb(int nb, int n) {
    const int t = threadIdx.x;       // 128 threads
    int v = (t < nb) ? g_bsum[t] : 0;
    int own = v;
    int lane = t & 31, w = t >> 5;
#pragma unroll
    for (int off = 1; off < 32; off <<= 1) {
        int u = __shfl_up_sync(0xffffffffu, v, off);
        if (lane >= off) v += u;
    }
    __shared__ int wtot[4], woff[4];
    if (lane == 31) wtot[w] = v;
    __syncthreads();
    if (t == 0) {
        int run = 0;
#pragma unroll
        for (int i = 0; i < 4; i++) { woff[i] = run; run += wtot[i]; }
        g_rowptr[n] = run;           // total edge count
    }
    __syncthreads();
    int incl = v + woff[w];
    if (t < nb) g_boff[t] = incl - own;   // exclusive
}

__global__ void k_rowptr(int n) {
    const int t = threadIdx.x;       // 256 threads
    const int base = blockIdx.x * SCAN_CHUNK + t * 4;
    int c[4];
    int s = 0;
#pragma unroll
    for (int j = 0; j < 4; j++) {
        int i = base + j;
        c[j] = (i < n) ? g_cnt[i] : 0;
        s += c[j];
    }
    int v = s, own = s;
    int lane = t & 31, w = t >> 5;
#pragma unroll
    for (int off = 1; off < 32; off <<= 1) {
        int u = __shfl_up_sync(0xffffffffu, v, off);
        if (lane >= off) v += u;
    }
    __shared__ int wtot[8], woff[8];
    if (lane == 31) wtot[w] = v;
    __syncthreads();
    if (t == 0) {
        int run = 0;
#pragma unroll
        for (int i = 0; i < 8; i++) { woff[i] = run; run += wtot[i]; }
    }
    __syncthreads();
    int excl = (v - own) + woff[w] + g_boff[blockIdx.x];
#pragma unroll
    for (int j = 0; j < 4; j++) {
        int i = base + j;
        if (i < n) {
            g_rowptr[i] = excl;
            excl += c[j];
            g_cnt[i] = 0;            // reset fill cursor
        }
    }
}

// Scatter edges into CSR slots (by dst). Order within a row is arbitrary.
__global__ void k_fill(const int* __restrict__ ei, int e, int n) {
    int idx = blockIdx.x * blockDim.x + threadIdx.x;
    if (idx < e) {
        int s = ei[idx];
        int d = ei[e + idx];
        if (s >= 0 && s < n && d >= 0 && d < n) {
            int pos = g_rowptr[d] + atomicAdd(&g_cnt[d], 1);
            if (pos < EMAX) g_eidx[pos] = s;
        }
    }
}

// ---------------------------------------------------------------------------
// t2 = dinv ⊙ ((relu?)hin @ W), written as fp32 (self term) AND fp16 (messages)
__global__ void k_matmul(const float* __restrict__ xin, int use_x,
                         const float* __restrict__ W, int n, int relu) {
    __shared__ float Hsh[64 * 68];   // stride 68: 16B-aligned rows, conflict-free
    __shared__ float Wsh[64 * 64];

    const float* hin = use_x ? xin : g_h;

    const int tid = threadIdx.x;
    const int r0  = blockIdx.x * 64;

    // Load W (64x64) coalesced
    const float4* W4 = (const float4*)W;
    float4* Wsh4 = (float4*)Wsh;
#pragma unroll
    for (int i = 0; i < 4; i++) Wsh4[tid + 256 * i] = W4[tid + 256 * i];

    // Load H tile (64 rows x 64 cols), optional relu
#pragma unroll
    for (int i = 0; i < 4; i++) {
        int idx = tid + 256 * i;         // 0..1023 float4 slots
        int row = idx >> 4;
        int c4  = idx & 15;
        int gr  = r0 + row;
        float4 v = make_float4(0.f, 0.f, 0.f, 0.f);
        if (gr < n) v = *(const float4*)(hin + (size_t)gr * 64 + c4 * 4);
        if (relu) {
            v.x = fmaxf(v.x, 0.f); v.y = fmaxf(v.y, 0.f);
            v.z = fmaxf(v.z, 0.f); v.w = fmaxf(v.w, 0.f);
        }
        float* hp = &Hsh[row * 68 + c4 * 4];
        hp[0] = v.x; hp[1] = v.y; hp[2] = v.z; hp[3] = v.w;
    }
    __syncthreads();

    const int row = tid >> 2;          // 0..63
    const int cb  = (tid & 3) * 16;    // col base
    float acc[16];
#pragma unroll
    for (int j = 0; j < 16; j++) acc[j] = 0.f;

#pragma unroll 16
    for (int k = 0; k < 64; k++) {
        float hk = Hsh[row * 68 + k];
#pragma unroll
        for (int j = 0; j < 16; j++)
            acc[j] = fmaf(hk, Wsh[k * 64 + cb + j], acc[j]);
    }

    const int gr = r0 + row;
    if (gr < n) {
        float di = g_dinv[gr];
        size_t base = (size_t)gr * 64 + cb;
        uint2 hpack[4];
#pragma unroll
        for (int j = 0; j < 16; j += 4) {
            float4 t;
            t.x = di * acc[j + 0]; t.y = di * acc[j + 1];
            t.z = di * acc[j + 2]; t.w = di * acc[j + 3];
            *(float4*)(g_t2 + base + j) = t;
            __half2 p0 = __floats2half2_rn(t.x, t.y);
            __half2 p1 = __floats2half2_rn(t.z, t.w);
            hpack[j >> 2].x = *(const unsigned int*)&p0;
            hpack[j >> 2].y = *(const unsigned int*)&p1;
        }
        // 16 fp16 = 32B per thread, contiguous
        uint4 hp4;
        hp4.x = hpack[0].x; hp4.y = hpack[0].y;
        hp4.z = hpack[1].x; hp4.w = hpack[1].y;
        *(uint4*)(g_t2h + base)     = hp4;
        hp4.x = hpack[2].x; hp4.y = hpack[2].y;
        hp4.z = hpack[3].x; hp4.w = hpack[3].y;
        *(uint4*)(g_t2h + base + 8) = hp4;
    }
}

// ---------------------------------------------------------------------------
// Gather: h[i] = dinv[i]*(t2[i] + sum_{e: dst=i} fp16(t2[src_e])) + b
// 16 threads per node; neighbor rows read as fp16 (8 B/thread), fp32 accum.
__global__ void k_gather(const float* __restrict__ b, int n) {
    int gid = blockIdx.x * blockDim.x + threadIdx.x;
    int node = gid >> 4;
    if (node >= n) return;
    int q = (gid & 15) << 2;

    float4 acc = *(const float4*)(g_t2 + ((size_t)node << 6) + q);
    float4 acc2 = make_float4(0.f, 0.f, 0.f, 0.f);

    int k   = g_rowptr[node];
    int end = g_rowptr[node + 1];

    const __half* t2h = g_t2h;

    for (; k + 4 <= end; k += 4) {
        int s0 = __ldg(&g_eidx[k]);
        int s1 = __ldg(&g_eidx[k + 1]);
        int s2 = __ldg(&g_eidx[k + 2]);
        int s3 = __ldg(&g_eidx[k + 3]);
        uint2 r0 = *(const uint2*)(t2h + ((size_t)s0 << 6) + q);
        uint2 r1 = *(const uint2*)(t2h + ((size_t)s1 << 6) + q);
        uint2 r2 = *(const uint2*)(t2h + ((size_t)s2 << 6) + q);
        uint2 r3 = *(const uint2*)(t2h + ((size_t)s3 << 6) + q);
        float2 a0 = __half22float2(*(const __half2*)&r0.x);
        float2 b0 = __half22float2(*(const __half2*)&r0.y);
        float2 a1 = __half22float2(*(const __half2*)&r1.x);
        float2 b1 = __half22float2(*(const __half2*)&r1.y);
        float2 a2 = __half22float2(*(const __half2*)&r2.x);
        float2 b2 = __half22float2(*(const __half2*)&r2.y);
        float2 a3 = __half22float2(*(const __half2*)&r3.x);
        float2 b3 = __half22float2(*(const __half2*)&r3.y);
        acc.x  += a0.x + a1.x;  acc.y  += a0.y + a1.y;
        acc.z  += b0.x + b1.x;  acc.w  += b0.y + b1.y;
        acc2.x += a2.x + a3.x;  acc2.y += a2.y + a3.y;
        acc2.z += b2.x + b3.x;  acc2.w += b2.y + b3.y;
    }
    for (; k < end; k++) {
        int s0 = __ldg(&g_eidx[k]);
        uint2 r0 = *(const uint2*)(t2h + ((size_t)s0 << 6) + q);
        float2 a0 = __half22float2(*(const __half2*)&r0.x);
        float2 b0 = __half22float2(*(const __half2*)&r0.y);
        acc.x += a0.x; acc.y += a0.y; acc.z += b0.x; acc.w += b0.y;
    }
    acc.x += acc2.x; acc.y += acc2.y; acc.z += acc2.z; acc.w += acc2.w;

    float di = g_dinv[node];
    float4 bb = *(const float4*)(b + q);
    float4 o;
    o.x = fmaf(di, acc.x, bb.x);
    o.y = fmaf(di, acc.y, bb.y);
    o.z = fmaf(di, acc.z, bb.z);
    o.w = fmaf(di, acc.w, bb.w);
    *(float4*)(g_h + ((size_t)node << 6) + q) = o;
}

// ---------------------------------------------------------------------------
// Fused mean-pool (batch sorted -> binary search segments) + linear head.
__global__ void k_pool(const int* __restrict__ batch,
                       const float* __restrict__ Wl, const float* __restrict__ bl,
                       float* __restrict__ out, int n) {
    const float* h = g_h;
    const int g = blockIdx.x;
    const int t = threadIdx.x;
    const int c = t & 63;
    const int j = t >> 6;

    auto lb = [&](int key) {
        int lo = 0, hi = n;
        while (lo < hi) {
            int mid = (lo + hi) >> 1;
            if (batch[mid] < key) lo = mid + 1; else hi = mid;
        }
        return lo;
    };
    int lo = lb(g);
    int hi = lb(g + 1);
    int cnt = hi - lo;

    float s = 0.f;
    for (int i = lo + j; i < hi; i += 4)
        s += h[(size_t)i * 64 + c];

    __shared__ float red[256];
    red[t] = s;
    __syncthreads();

    __shared__ float pooled[64];
    if (t < 64) {
        float tot = red[t] + red[t + 64] + red[t + 128] + red[t + 192];
        pooled[t] = tot / (float)max(cnt, 1);
    }
    __syncthreads();

    if (t < NCLS) {
        float acc = bl[t];
#pragma unroll
        for (int k = 0; k < 64; k++)
            acc = fmaf(pooled[k], Wl[k * NCLS + t], acc);
        out[g * NCLS + t] = acc;
    }
}

// ---------------------------------------------------------------------------
extern "C" void kernel_launch(void* const* d_in, const int* in_sizes, int n_in,
                              void* d_out, int out_size) {
    // Resolve inputs BY ELEMENT COUNT (robust to metadata ordering).
    const float* x     = nullptr;
    const int*   ei    = nullptr;
    const int*   batch = nullptr;
    const float* W[3] = {nullptr, nullptr, nullptr};
    const float* B[3] = {nullptr, nullptr, nullptr};
    const float* Wl = nullptr;
    const float* bl = nullptr;
    int nW = 0, nB = 0;
    long long eiCount = 0, batchCount = 0;

    for (int i = 0; i < n_in; i++) {
        long long sz = in_sizes[i];
        if (sz == 10)            bl = (const float*)d_in[i];
        else if (sz == 640)      Wl = (const float*)d_in[i];
        else if (sz == HDIM)     { if (nB < 3) B[nB++] = (const float*)d_in[i]; }
        else if (sz == HDIM*HDIM){ if (nW < 3) W[nW++] = (const float*)d_in[i]; }
        else {
            if (sz >= 6000000)       x = (const float*)d_in[i];
            else if (sz >= 2000000)  { ei = (const int*)d_in[i]; eiCount = sz; }
            else                     { batch = (const int*)d_in[i]; batchCount = sz; }
        }
    }

    float* out = (float*)d_out;
    const int n = (int)batchCount;            // N nodes
    const int e = (int)(eiCount / 2);         // E edges
    const int g = out_size / NCLS;            // G graphs

    const int tb = 256;
    const int nb = (n + SCAN_CHUNK - 1) / SCAN_CHUNK;   // scan blocks (98)
    const int mmGrid = (n + 63) / 64;
    const int gaGrid = (n * 16 + tb - 1) / tb;

    // Launch order puts matmul layer-1 at slot #4 (the ncu-captured launch).
    k_zerocnt <<<(n + tb - 1) / tb, tb>>>(n);            // 1
    k_hist    <<<(e + tb - 1) / tb, tb>>>(ei, e, n);     // 2
    k_dinvk   <<<(n + tb - 1) / tb, tb>>>(n);            // 3
    k_matmul  <<<mmGrid, tb>>>(x, 1, W[0], n, 0);        // 4  <- profiled
    k_blocksum<<<nb, tb>>>(n);                           // 5
    k_scanb   <<<1, 128>>>(nb, n);                       // 6
    k_rowptr  <<<nb, tb>>>(n);                           // 7
    k_fill    <<<(e + tb - 1) / tb, tb>>>(ei, e, n);     // 8
    k_gather  <<<gaGrid, tb>>>(B[0], n);                 // 9
    k_matmul  <<<mmGrid, tb>>>(nullptr, 0, W[1], n, 1);  // 10
    k_gather  <<<gaGrid, tb>>>(B[1], n);                 // 11
    k_matmul  <<<mmGrid, tb>>>(nullptr, 0, W[2], n, 1);  // 12
    k_gather  <<<gaGrid, tb>>>(B[2], n);                 // 13
    k_pool    <<<g, tb>>>(batch, Wl, bl, out, n);        // 14
}

// round 11
// speedup vs baseline: 2.7227x; 2.0051x over previous
#include <cuda_runtime.h>
#include <cuda_fp16.h>
#include <cstdint>

// Problem constants (fixed by the reference)
#define NMAX 100000
#define EMAX 1250000
#define HDIM 64
#define NCLS 10
#define SCAN_CHUNK 1024
#define MAXBLK 128   // ceil(NMAX/SCAN_CHUNK) = 98 <= 128

typedef unsigned long long ull;

// Packed fp32x2 helpers (Blackwell PTX; rounding identical to fmaf)
#define FMA2(d, a, b, c) \
    asm("fma.rn.f32x2 %0, %1, %2, %3;" : "=l"(d) : "l"(a), "l"(b), "l"(c))
#define PACK2(out, lo, hi) \
    asm("mov.b64 %0, {%1, %2};" : "=l"(out) : "f"(lo), "f"(hi))
#define UNPACK2(lo, hi, in) \
    asm("mov.b64 {%0, %1}, %2;" : "=f"(lo), "=f"(hi) : "l"(in))

// Scratch: __device__ globals (allocation APIs are forbidden).
__device__ __align__(16)  float  g_t2[NMAX * HDIM];   // fp32 messages (self term)
__device__ __align__(128) __half g_t2h[NMAX * HDIM];  // fp16 messages (neighbor reads)
__device__ __align__(16)  float  g_h [NMAX * HDIM];   // layer output
__device__ float g_dinv[NMAX];
__device__ int   g_cnt[NMAX];
__device__ int   g_rowptr[NMAX + 1];
__device__ int   g_eidx[EMAX];
__device__ int   g_bsum[MAXBLK];
__device__ int   g_boff[MAXBLK];

// ---------------------------------------------------------------------------
__global__ void k_zerocnt(int n) {
    int i = blockIdx.x * blockDim.x + threadIdx.x;
    if (i < n) g_cnt[i] = 0;
}

__global__ void k_hist(const int* __restrict__ ei, int e, int n) {
    int idx = blockIdx.x * blockDim.x + threadIdx.x;
    if (idx < e) {
        int d = ei[e + idx];
        if (d >= 0 && d < n) atomicAdd(&g_cnt[d], 1);
    }
}

__global__ void k_dinvk(int n) {
    int i = blockIdx.x * blockDim.x + threadIdx.x;
    if (i < n) g_dinv[i] = rsqrtf((float)(g_cnt[i] + 1));
}

// ---------------------------------------------------------------------------
// Parallel 3-phase exclusive scan of g_cnt -> g_rowptr.
__global__ void k_blocksum(int n) {
    const int t = threadIdx.x;
    const int base = blockIdx.x * SCAN_CHUNK + t * 4;
    int s = 0;
#pragma unroll
    for (int j = 0; j < 4; j++) {
        int i = base + j;
        if (i < n) s += g_cnt[i];
    }
#pragma unroll
    for (int off = 16; off > 0; off >>= 1)
        s += __shfl_down_sync(0xffffffffu, s, off);
    __shared__ int wsum[8];
    if ((t & 31) == 0) wsum[t >> 5] = s;
    __syncthreads();
    if (t == 0) {
        int tot = 0;
#pragma unroll
        for (int w = 0; w < 8; w++) tot += wsum[w];
        g_bsum[blockIdx.x] = tot;
    }
}

__global__ void k_scanb(int nb, int n) {
    const int t = threadIdx.x;       // 128 threads
    int v = (t < nb) ? g_bsum[t] : 0;
    int own = v;
    int lane = t & 31, w = t >> 5;
#pragma unroll
    for (int off = 1; off < 32; off <<= 1) {
        int u = __shfl_up_sync(0xffffffffu, v, off);
        if (lane >= off) v += u;
    }
    __shared__ int wtot[4], woff[4];
    if (lane == 31) wtot[w] = v;
    __syncthreads();
    if (t == 0) {
        int run = 0;
#pragma unroll
        for (int i = 0; i < 4; i++) { woff[i] = run; run += wtot[i]; }
        g_rowptr[n] = run;           // total edge count
    }
    __syncthreads();
    int incl = v + woff[w];
    if (t < nb) g_boff[t] = incl - own;   // exclusive
}

__global__ void k_rowptr(int n) {
    const int t = threadIdx.x;       // 256 threads
    const int base = blockIdx.x * SCAN_CHUNK + t * 4;
    int c[4];
    int s = 0;
#pragma unroll
    for (int j = 0; j < 4; j++) {
        int i = base + j;
        c[j] = (i < n) ? g_cnt[i] : 0;
        s += c[j];
    }
    int v = s, own = s;
    int lane = t & 31, w = t >> 5;
#pragma unroll
    for (int off = 1; off < 32; off <<= 1) {
        int u = __shfl_up_sync(0xffffffffu, v, off);
        if (lane >= off) v += u;
    }
    __shared__ int wtot[8], woff[8];
    if (lane == 31) wtot[w] = v;
    __syncthreads();
    if (t == 0) {
        int run = 0;
#pragma unroll
        for (int i = 0; i < 8; i++) { woff[i] = run; run += wtot[i]; }
    }
    __syncthreads();
    int excl = (v - own) + woff[w] + g_boff[blockIdx.x];
#pragma unroll
    for (int j = 0; j < 4; j++) {
        int i = base + j;
        if (i < n) {
            g_rowptr[i] = excl;
            excl += c[j];
            g_cnt[i] = 0;            // reset fill cursor
        }
    }
}

__global__ void k_fill(const int* __restrict__ ei, int e, int n) {
    int idx = blockIdx.x * blockDim.x + threadIdx.x;
    if (idx < e) {
        int s = ei[idx];
        int d = ei[e + idx];
        if (s >= 0 && s < n && d >= 0 && d < n) {
            int pos = g_rowptr[d] + atomicAdd(&g_cnt[d], 1);
            if (pos < EMAX) g_eidx[pos] = s;
        }
    }
}

// ---------------------------------------------------------------------------
// Register-tiled GEMM: t2 = dinv ⊙ ((relu?)hin @ W), fp32 + fp16 outputs.
// BM=128 rows/block, 128 threads: ty=tid>>3 (16), tx=tid&7 (8).
// Thread computes rows {ty+16*i, i=0..7} x cols [tx*8, tx*8+8).
// Hsh XOR-swizzled so the 8 per-row scalar loads are bank-conflict-free.
// Accumulation via packed fma.rn.f32x2 (2 fp32 FMA per instruction).
__global__ void __launch_bounds__(128) k_matmul(
        const float* __restrict__ xin, int use_x,
        const float* __restrict__ W, int n, int relu) {
    __shared__ float Hsh[128 * 64];  // [row][k ^ ((row&3)<<3)]
    __shared__ float Wsh[64 * 64];   // [k][col]

    const float* hin = use_x ? xin : g_h;
    const int tid = threadIdx.x;
    const int r0  = blockIdx.x * 128;

    // Load W (64x64) coalesced: 1024 float4 / 128 threads = 8 iters
    {
        const float4* W4 = (const float4*)W;
        float4* Wsh4 = (float4*)Wsh;
#pragma unroll
        for (int i = 0; i < 8; i++) Wsh4[tid + 128 * i] = W4[tid + 128 * i];
    }

    // Load H tile (128 rows x 64 cols) with XOR swizzle, optional relu.
#pragma unroll
    for (int i = 0; i < 16; i++) {
        int idx = tid + 128 * i;        // 0..2047 float4 slots
        int row = idx >> 4;
        int c4  = idx & 15;
        int gr  = r0 + row;
        float4 v = make_float4(0.f, 0.f, 0.f, 0.f);
        if (gr < n) v = *(const float4*)(hin + (size_t)gr * 64 + c4 * 4);
        if (relu) {
            v.x = fmaxf(v.x, 0.f); v.y = fmaxf(v.y, 0.f);
            v.z = fmaxf(v.z, 0.f); v.w = fmaxf(v.w, 0.f);
        }
        int col = (c4 * 4) ^ ((row & 3) << 3);   // swizzled column base
        *(float4*)&Hsh[row * 64 + col] = v;
    }
    __syncthreads();

    const int ty = tid >> 3;         // 0..15
    const int tx = tid & 7;          // 0..7
    const int kswz = (ty & 3) << 3;  // per-thread constant XOR

    ull acc[8][4];
#pragma unroll
    for (int i = 0; i < 8; i++)
#pragma unroll
        for (int j = 0; j < 4; j++) acc[i][j] = 0ull;

#pragma unroll 4
    for (int k = 0; k < 64; k++) {
        const int kx = k ^ kswz;
        ull ad[8];
#pragma unroll
        for (int i = 0; i < 8; i++) {
            float a = Hsh[(ty + 16 * i) * 64 + kx];
            PACK2(ad[i], a, a);
        }
        const ull* Wp = (const ull*)(Wsh + k * 64 + tx * 8);
        ull b0 = Wp[0], b1 = Wp[1], b2 = Wp[2], b3 = Wp[3];
#pragma unroll
        for (int i = 0; i < 8; i++) {
            FMA2(acc[i][0], ad[i], b0, acc[i][0]);
            FMA2(acc[i][1], ad[i], b1, acc[i][1]);
            FMA2(acc[i][2], ad[i], b2, acc[i][2]);
            FMA2(acc[i][3], ad[i], b3, acc[i][3]);
        }
    }

    // Epilogue: scale by dinv, write fp32 t2 + fp16 t2h
#pragma unroll
    for (int i = 0; i < 8; i++) {
        int row = r0 + ty + 16 * i;
        if (row >= n) continue;
        float di = g_dinv[row];
        float o[8];
#pragma unroll
        for (int j = 0; j < 4; j++) {
            float lo, hi;
            UNPACK2(lo, hi, acc[i][j]);
            o[2 * j]     = lo * di;
            o[2 * j + 1] = hi * di;
        }
        size_t base = (size_t)row * 64 + tx * 8;
        *(float4*)(g_t2 + base)     = make_float4(o[0], o[1], o[2], o[3]);
        *(float4*)(g_t2 + base + 4) = make_float4(o[4], o[5], o[6], o[7]);
        __half2 h0 = __floats2half2_rn(o[0], o[1]);
        __half2 h1 = __floats2half2_rn(o[2], o[3]);
        __half2 h2 = __floats2half2_rn(o[4], o[5]);
        __half2 h3 = __floats2half2_rn(o[6], o[7]);
        uint4 hp;
        hp.x = *(const unsigned int*)&h0;
        hp.y = *(const unsigned int*)&h1;
        hp.z = *(const unsigned int*)&h2;
        hp.w = *(const unsigned int*)&h3;
        *(uint4*)(g_t2h + base) = hp;
    }
}

// ---------------------------------------------------------------------------
// Gather: h[i] = dinv[i]*(t2[i] + sum_{e: dst=i} fp16(t2[src_e])) + b
// 16 threads per node; neighbor rows read as fp16 (8 B/thread), fp32 accum.
__global__ void k_gather(const float* __restrict__ b, int n) {
    int gid = blockIdx.x * blockDim.x + threadIdx.x;
    int node = gid >> 4;
    if (node >= n) return;
    int q = (gid & 15) << 2;

    float4 acc = *(const float4*)(g_t2 + ((size_t)node << 6) + q);
    float4 acc2 = make_float4(0.f, 0.f, 0.f, 0.f);

    int k   = g_rowptr[node];
    int end = g_rowptr[node + 1];

    const __half* t2h = g_t2h;

    for (; k + 4 <= end; k += 4) {
        int s0 = __ldg(&g_eidx[k]);
        int s1 = __ldg(&g_eidx[k + 1]);
        int s2 = __ldg(&g_eidx[k + 2]);
        int s3 = __ldg(&g_eidx[k + 3]);
        uint2 r0 = *(const uint2*)(t2h + ((size_t)s0 << 6) + q);
        uint2 r1 = *(const uint2*)(t2h + ((size_t)s1 << 6) + q);
        uint2 r2 = *(const uint2*)(t2h + ((size_t)s2 << 6) + q);
        uint2 r3 = *(const uint2*)(t2h + ((size_t)s3 << 6) + q);
        float2 a0 = __half22float2(*(const __half2*)&r0.x);
        float2 b0 = __half22float2(*(const __half2*)&r0.y);
        float2 a1 = __half22float2(*(const __half2*)&r1.x);
        float2 b1 = __half22float2(*(const __half2*)&r1.y);
        float2 a2 = __half22float2(*(const __half2*)&r2.x);
        float2 b2 = __half22float2(*(const __half2*)&r2.y);
        float2 a3 = __half22float2(*(const __half2*)&r3.x);
        float2 b3 = __half22float2(*(const __half2*)&r3.y);
        acc.x  += a0.x + a1.x;  acc.y  += a0.y + a1.y;
        acc.z  += b0.x + b1.x;  acc.w  += b0.y + b1.y;
        acc2.x += a2.x + a3.x;  acc2.y += a2.y + a3.y;
        acc2.z += b2.x + b3.x;  acc2.w += b2.y + b3.y;
    }
    for (; k < end; k++) {
        int s0 = __ldg(&g_eidx[k]);
        uint2 r0 = *(const uint2*)(t2h + ((size_t)s0 << 6) + q);
        float2 a0 = __half22float2(*(const __half2*)&r0.x);
        float2 b0 = __half22float2(*(const __half2*)&r0.y);
        acc.x += a0.x; acc.y += a0.y; acc.z += b0.x; acc.w += b0.y;
    }
    acc.x += acc2.x; acc.y += acc2.y; acc.z += acc2.z; acc.w += acc2.w;

    float di = g_dinv[node];
    float4 bb = *(const float4*)(b + q);
    float4 o;
    o.x = fmaf(di, acc.x, bb.x);
    o.y = fmaf(di, acc.y, bb.y);
    o.z = fmaf(di, acc.z, bb.z);
    o.w = fmaf(di, acc.w, bb.w);
    *(float4*)(g_h + ((size_t)node << 6) + q) = o;
}

// ---------------------------------------------------------------------------
// Fused mean-pool (batch sorted -> binary search segments) + linear head.
__global__ void k_pool(const int* __restrict__ batch,
                       const float* __restrict__ Wl, const float* __restrict__ bl,
                       float* __restrict__ out, int n) {
    const float* h = g_h;
    const int g = blockIdx.x;
    const int t = threadIdx.x;
    const int c = t & 63;
    const int j = t >> 6;

    auto lb = [&](int key) {
        int lo = 0, hi = n;
        while (lo < hi) {
            int mid = (lo + hi) >> 1;
            if (batch[mid] < key) lo = mid + 1; else hi = mid;
        }
        return lo;
    };
    int lo = lb(g);
    int hi = lb(g + 1);
    int cnt = hi - lo;

    float s = 0.f;
    for (int i = lo + j; i < hi; i += 4)
        s += h[(size_t)i * 64 + c];

    __shared__ float red[256];
    red[t] = s;
    __syncthreads();

    __shared__ float pooled[64];
    if (t < 64) {
        float tot = red[t] + red[t + 64] + red[t + 128] + red[t + 192];
        pooled[t] = tot / (float)max(cnt, 1);
    }
    __syncthreads();

    if (t < NCLS) {
        float acc = bl[t];
#pragma unroll
        for (int k = 0; k < 64; k++)
            acc = fmaf(pooled[k], Wl[k * NCLS + t], acc);
        out[g * NCLS + t] = acc;
    }
}

// ---------------------------------------------------------------------------
extern "C" void kernel_launch(void* const* d_in, const int* in_sizes, int n_in,
                              void* d_out, int out_size) {
    // Resolve inputs BY ELEMENT COUNT (robust to metadata ordering).
    const float* x     = nullptr;
    const int*   ei    = nullptr;
    const int*   batch = nullptr;
    const float* W[3] = {nullptr, nullptr, nullptr};
    const float* B[3] = {nullptr, nullptr, nullptr};
    const float* Wl = nullptr;
    const float* bl = nullptr;
    int nW = 0, nB = 0;
    long long eiCount = 0, batchCount = 0;

    for (int i = 0; i < n_in; i++) {
        long long sz = in_sizes[i];
        if (sz == 10)            bl = (const float*)d_in[i];
        else if (sz == 640)      Wl = (const float*)d_in[i];
        else if (sz == HDIM)     { if (nB < 3) B[nB++] = (const float*)d_in[i]; }
        else if (sz == HDIM*HDIM){ if (nW < 3) W[nW++] = (const float*)d_in[i]; }
        else {
            if (sz >= 6000000)       x = (const float*)d_in[i];
            else if (sz >= 2000000)  { ei = (const int*)d_in[i]; eiCount = sz; }
            else                     { batch = (const int*)d_in[i]; batchCount = sz; }
        }
    }

    float* out = (float*)d_out;
    const int n = (int)batchCount;            // N nodes
    const int e = (int)(eiCount / 2);         // E edges
    const int g = out_size / NCLS;            // G graphs

    const int tb = 256;
    const int nb = (n + SCAN_CHUNK - 1) / SCAN_CHUNK;   // scan blocks (98)
    const int mmGrid = (n + 127) / 128;
    const int gaGrid = (n * 16 + tb - 1) / tb;

    // Launch order keeps matmul layer-1 at slot #4 (the ncu-captured launch).
    k_zerocnt <<<(n + tb - 1) / tb, tb>>>(n);            // 1
    k_hist    <<<(e + tb - 1) / tb, tb>>>(ei, e, n);     // 2
    k_dinvk   <<<(n + tb - 1) / tb, tb>>>(n);            // 3
    k_matmul  <<<mmGrid, 128>>>(x, 1, W[0], n, 0);       // 4  <- profiled
    k_blocksum<<<nb, tb>>>(n);                           // 5
    k_scanb   <<<1, 128>>>(nb, n);                       // 6
    k_rowptr  <<<nb, tb>>>(n);                           // 7
    k_fill    <<<(e + tb - 1) / tb, tb>>>(ei, e, n);     // 8
    k_gather  <<<gaGrid, tb>>>(B[0], n);                 // 9
    k_matmul  <<<mmGrid, 128>>>(nullptr, 0, W[1], n, 1); // 10
    k_gather  <<<gaGrid, tb>>>(B[1], n);                 // 11
    k_matmul  <<<mmGrid, 128>>>(nullptr, 0, W[2], n, 1); // 12
    k_gather  <<<gaGrid, tb>>>(B[2], n);                 // 13
    k_pool    <<<g, tb>>>(batch, Wl, bl, out, n);        // 14
}